// round 11
// baseline (speedup 1.0000x reference)
#include <cuda_runtime.h>
#include <math.h>

// Problem constants
#define BB    128
#define KTOT  8194             // pos (2) + neg (8192)
#define NMEM  100000
#define TAU_INV 14.2857142857142857f   // 1/0.07
#define KDT_F 3.0f
#define N4    (NMEM * 32)      // float4 per mem = 3,200,000
#define NGRP  2049             // ceil(KTOT/4) groups of 4 k's
#define SPLITS 3
#define COPYB  60
#define GATHB  (BB * SPLITS)   // 384 gather CTAs
#define TOTB   (COPYB + GATHB) // 444 = 148 SMs x occ 3 -> single exact wave

// Per-(b,split) partials: [0..2]=cij(T,1,W) [3..5]=cji [6..8]=intra0 [9..11]=intra1
__device__ float g_part2[BB][SPLITS][12];
// Per-b specials: [a0, c0, a1, c1, ia1, ib1]
__device__ float g_spec[BB][6];
__device__ unsigned int g_ctr = 0;

// packed fp32 FMA (sm_103a f32x2 pipe; ptxas never auto-fuses this)
__device__ __forceinline__ void ffma2(unsigned long long& acc,
                                      unsigned long long a,
                                      unsigned long long b) {
    asm("fma.rn.f32x2 %0, %1, %2, %0;" : "+l"(acc) : "l"(a), "l"(b));
}
__device__ __forceinline__ float hsum2(unsigned long long v) {
    float lo, hi;
    asm("mov.b64 {%0,%1}, %2;" : "=f"(lo), "=f"(hi) : "l"(v));
    return lo + hi;
}

// ---------------------------------------------------------------------------
// Big kernel. CTAs [0,COPYB): stream fp32 mems -> out (DRAM path, cache-
// streaming both ways so the gather keeps L2). CTAs [COPYB,TOTB): gather.
// Gather: quarter-warp (8 lanes x 16 dims) per k; 4 k per warp-group;
// all four dot products in f32x2; exp-sums folded inline (1 MUFU / 4 k).
// Last CTA (atomic counter) does the scalar reduce + momentum update.
// ---------------------------------------------------------------------------
__global__ void __launch_bounds__(256, 3)
big_kernel(const float* __restrict__ emb0,
           const float* __restrict__ emb1,
           const float4* __restrict__ mem0,
           const float4* __restrict__ mem1,
           const int*   __restrict__ pos_idx,
           const int*   __restrict__ neg_idx,
           float* __restrict__ out)
{
    const int bid  = blockIdx.x;
    const int tid  = threadIdx.x;
    const int lane = tid & 31;
    const int warp = tid >> 5;

    if (bid < COPYB) {
        // ---- streaming copy: new_mems baseline ----
        float4* dst = reinterpret_cast<float4*>(out + 4);
        const int stride = COPYB * 256;
        for (int i = bid * 256 + tid; i < N4; i += stride) {
            float4 a = __ldcs(mem0 + i);
            float4 c = __ldcs(mem1 + i);
            __stcs(dst + i,      a);
            __stcs(dst + N4 + i, c);
        }
    } else {
        // ---- gather CTA: one (b, split) per CTA ----
        const int id    = bid - COPYB;
        const int b     = id & (BB - 1);
        const int split = id >> 7;          // 0..SPLITS-1
        const int grp   = lane >> 3;        // quarter-warp: one k each
        const int gl    = lane & 7;
        const int j     = lane & 3;         // accumulator array for this lane

        // emb fragments as f32x2 pairs: lane owns float4 slots {gl,gl+8,gl+16,gl+24}
        const ulonglong2* e0p = reinterpret_cast<const ulonglong2*>(emb0) + b * 32;
        const ulonglong2* e1p = reinterpret_cast<const ulonglong2*>(emb1) + b * 32;
        ulonglong2 e0f[4], e1f[4];
#pragma unroll
        for (int i = 0; i < 4; i++) {
            e0f[i] = e0p[gl + 8*i];
            e1f[i] = e1p[gl + 8*i];
        }

        float accT = 0.f, acc1 = 0.f, accW = 0.f;

        for (int g = split * 8 + warp; g < NGRP; g += SPLITS * 8) {
            const int  k       = g * 4 + grp;
            const bool v_inter = (k < KTOT);
            int r = 0;
            if (v_inter) r = (k < 2) ? pos_idx[b*2 + k] : neg_idx[b*8192 + (k - 2)];
            const ulonglong2* M0 =
                reinterpret_cast<const ulonglong2*>(mem0 + (size_t)r * 32);
            const ulonglong2* M1 =
                reinterpret_cast<const ulonglong2*>(mem1 + (size_t)r * 32);

            unsigned long long s01 = 0ull, s10 = 0ull, si0 = 0ull, si1 = 0ull;
#pragma unroll
            for (int i = 0; i < 4; i++) {
                ulonglong2 m0 = M0[gl + 8*i];   // 8 lanes -> one 128B line
                ulonglong2 m1 = M1[gl + 8*i];
                ffma2(s01, m0.x, e1f[i].x);  ffma2(s01, m0.y, e1f[i].y);  // cij
                ffma2(si0, m0.x, e0f[i].x);  ffma2(si0, m0.y, e0f[i].y);  // intra0
                ffma2(s10, m1.x, e0f[i].x);  ffma2(s10, m1.y, e0f[i].y);  // cji
                ffma2(si1, m1.x, e1f[i].x);  ffma2(si1, m1.y, e1f[i].y);  // intra1
            }
            float f01 = hsum2(s01), f10 = hsum2(s10);
            float fi0 = hsum2(si0), fi1 = hsum2(si1);

            // reduce within the 8-lane quarter-warp
#pragma unroll
            for (int o = 4; o; o >>= 1) {
                f01 += __shfl_xor_sync(0xffffffffu, f01, o);
                f10 += __shfl_xor_sync(0xffffffffu, f10, o);
                fi0 += __shfl_xor_sync(0xffffffffu, fi0, o);
                fi1 += __shfl_xor_sync(0xffffffffu, fi1, o);
            }
            const float la  = f01 * TAU_INV;
            const float lc  = f10 * TAU_INV;
            const float lia = fi0 * TAU_INV;
            const float lib = fi1 * TAU_INV;

            if (g == 0) {                     // split 0, warp 0 only
                if (lane == 0) { g_spec[b][0] = la; g_spec[b][1] = lc; }   // k=0
                if (lane == 8) { g_spec[b][2] = la; g_spec[b][3] = lc;     // k=1
                                 g_spec[b][4] = lia; g_spec[b][5] = lib; }
            }

            // lane's (value, other) pair for its array j
            float v, o;
            if      (j == 0) { v = la;  o = lc;  }
            else if (j == 1) { v = lc;  o = la;  }
            else if (j == 2) { v = lia; o = lib; }
            else             { v = lib; o = lia; }
            const bool valid = (j < 2) ? v_inter : (v_inter && k >= 1);

            const float e3 = valid ? __expf(v * (1.0f/KDT_F)) : 0.f;  // exp(v/3)
            accT += e3;
            acc1 += e3 * e3 * e3;             // exp(v) = exp(v/3)^3
            accW += e3 * (v - o);
        }

        // xor4 folds the gl/gl+4 duplication (exact x2, halved below);
        // xor 8,16 fold the k-quarters.
#pragma unroll
        for (int o = 4; o <= 16; o <<= 1) {
            accT += __shfl_xor_sync(0xffffffffu, accT, o);
            acc1 += __shfl_xor_sync(0xffffffffu, acc1, o);
            accW += __shfl_xor_sync(0xffffffffu, accW, o);
        }

        __shared__ float sred[8][12];
        if (lane < 4) {
            sred[warp][lane*3 + 0] = accT * 0.5f;
            sred[warp][lane*3 + 1] = acc1 * 0.5f;
            sred[warp][lane*3 + 2] = accW * 0.5f;
        }
        __syncthreads();
        if (tid < 12) {
            float s = 0.f;
            for (int w = 0; w < 8; w++) s += sred[w][tid];   // fixed order
            g_part2[b][split][tid] = s;
        }
    }

    // ======================= fused finalize tail =======================
    __shared__ bool s_last;
    __syncthreads();
    if (tid == 0) {
        __threadfence();
        unsigned old = atomicAdd(&g_ctr, 1u);
        s_last = (old == TOTB - 1);
    }
    __syncthreads();
    if (!s_last) return;
    __threadfence();

    // ---- scalar reduce (threads 0..127) ----
    {
        float raw[4] = {0.f, 0.f, 0.f, 0.f};
        if (tid < BB) {
            float s2[12];
#pragma unroll
            for (int q = 0; q < 12; q++) {
                float a = 0.f;
                for (int sp = 0; sp < SPLITS; sp++) a += g_part2[tid][sp][q];
                s2[q] = a;
            }
            const float sAT = s2[0],  sA  = s2[1],  w1 = s2[2];
            const float sBT = s2[3],  sB  = s2[4],  w0 = s2[5];
            const float sIaT= s2[6],  sIa = s2[7],  w3 = s2[8];
            const float sIbT= s2[9],  sIb = s2[10], w2 = s2[11];
            const float LA  = logf(sA),  LB  = logf(sB);
            const float LIa = logf(sIa), LIb = logf(sIb);
            const float a0 = g_spec[tid][0], c0 = g_spec[tid][1];
            const float a1 = g_spec[tid][2], c1 = g_spec[tid][3];
            const float ia1 = g_spec[tid][4], ib1 = g_spec[tid][5];
            raw[0] = -(ia1 - LIa) - (ib1 - LIb);                     // vcl
            raw[1] = KDT_F * (w2 / sIbT + w3 / sIaT);                // soft_vcl
            raw[2] = -(0.5f*(a0+a1) - LA) - (0.5f*(c0+c1) - LB);     // icl
            raw[3] = KDT_F * (w0 / sBT + w1 / sAT);                  // soft_icl
        }
        __shared__ float scr[8][4];
#pragma unroll
        for (int q = 0; q < 4; q++) {
            float v = raw[q];
#pragma unroll
            for (int o = 16; o; o >>= 1) v += __shfl_xor_sync(0xffffffffu, v, o);
            if (lane == 0) scr[warp][q] = v;
        }
        __syncthreads();
        if (tid == 0) {
#pragma unroll
            for (int q = 0; q < 4; q++) {
                float v = 0.f;
                for (int w = 0; w < 8; w++) v += scr[w][q];
                out[q] = v / (float)BB;
            }
        }
    }

    // ---- momentum update: 256 warp-tasks (b, net), last-wins dedup ----
    for (int task = warp; task < 256; task += 8) {
        const int bb  = task & (BB - 1);
        const int net = task >> 7;
        const int r   = pos_idx[bb * 2];
        bool owner = true;
        for (int bp = bb + 1; bp < BB; bp++)
            if (pos_idx[bp * 2] == r) { owner = false; break; }
        if (!owner) continue;

        const float4* mem  = net ? mem1 : mem0;
        const float4* embp = reinterpret_cast<const float4*>(net ? emb1 : emb0);
        float4* dst = reinterpret_cast<float4*>(out + 4) + (size_t)net * N4;

        float4 m = mem[(size_t)r * 32 + lane];
        float4 e = embp[bb * 32 + lane];
        float4 u;
        u.x = 0.5f * (m.x + e.x);   // MOM = 0.5
        u.y = 0.5f * (m.y + e.y);
        u.z = 0.5f * (m.z + e.z);
        u.w = 0.5f * (m.w + e.w);
        float s2 = u.x*u.x + u.y*u.y + u.z*u.z + u.w*u.w;
#pragma unroll
        for (int o = 16; o; o >>= 1) s2 += __shfl_xor_sync(0xffffffffu, s2, o);
        const float inv = 1.0f / sqrtf(s2);
        u.x *= inv; u.y *= inv; u.z *= inv; u.w *= inv;
        dst[(size_t)r * 32 + lane] = u;
    }

    if (tid == 0) g_ctr = 0;   // reset for next graph replay
}

// ---------------------------------------------------------------------------
extern "C" void kernel_launch(void* const* d_in, const int* in_sizes, int n_in,
                              void* d_out, int out_size)
{
    const float* emb0    = (const float*)d_in[0];
    const float* emb1    = (const float*)d_in[1];
    const float* mem0    = (const float*)d_in[2];
    const float* mem1    = (const float*)d_in[3];
    const int*   pos_idx = (const int*)  d_in[4];
    const int*   neg_idx = (const int*)  d_in[5];
    float* out = (float*)d_out;

    // out layout: [vcl, soft_vcl, icl, soft_icl, new_mem0, new_mem1]
    big_kernel<<<TOTB, 256>>>(emb0, emb1,
                              (const float4*)mem0, (const float4*)mem1,
                              pos_idx, neg_idx, out);
}

// round 12
// speedup vs baseline: 1.0088x; 1.0088x over previous
#include <cuda_runtime.h>
#include <math.h>

// Problem constants
#define BB    128
#define KTOT  8194             // pos (2) + neg (8192)
#define NMEM  100000
#define TAU_INV 14.2857142857142857f   // 1/0.07
#define KDT_F 3.0f
#define N4    (NMEM * 32)      // float4 per mem = 3,200,000
#define NGRP  2049             // ceil(KTOT/4) groups of 4 k's
#define SPLITS 8
#define COPYB  128
#define GATHB  (BB * SPLITS)   // 1024 gather CTAs
#define TOTB   (COPYB + GATHB) // 1152 (R6 geometry: ~2 waves @ occ 4)

// Per-(b,split) partials: [0..2]=cij(T,1,W) [3..5]=cji [6..8]=intra0 [9..11]=intra1
__device__ float g_part2[BB][SPLITS][12];
// Per-b specials: [a0, c0, a1, c1, ia1, ib1]
__device__ float g_spec[BB][6];
__device__ unsigned int g_ctr = 0;

// packed fp32 FMA (sm_103a f32x2; ptxas never auto-fuses this)
__device__ __forceinline__ void ffma2(unsigned long long& acc,
                                      unsigned long long a,
                                      unsigned long long b) {
    asm("fma.rn.f32x2 %0, %1, %2, %0;" : "+l"(acc) : "l"(a), "l"(b));
}
__device__ __forceinline__ float hsum2(unsigned long long v) {
    float lo, hi;
    asm("mov.b64 {%0,%1}, %2;" : "=f"(lo), "=f"(hi) : "l"(v));
    return lo + hi;
}

// ---------------------------------------------------------------------------
// Big kernel (R6 geometry). CTAs [0,COPYB): stream fp32 mems -> out.
// CTAs [COPYB,TOTB): gather, quarter-warp (8 lanes x 16 dims) per k,
// 4 k per warp-group, dots in f32x2, exp-sums folded inline.
// Last CTA (atomic counter) does the scalar reduce + momentum update.
// ---------------------------------------------------------------------------
__global__ void __launch_bounds__(256, 4)
big_kernel(const float* __restrict__ emb0,
           const float* __restrict__ emb1,
           const float4* __restrict__ mem0,
           const float4* __restrict__ mem1,
           const int*   __restrict__ pos_idx,
           const int*   __restrict__ neg_idx,
           float* __restrict__ out)
{
    const int bid  = blockIdx.x;
    const int tid  = threadIdx.x;
    const int lane = tid & 31;
    const int warp = tid >> 5;

    if (bid < COPYB) {
        // ---- streaming copy: new_mems baseline (R6 layout) ----
        float4* dst = reinterpret_cast<float4*>(out + 4);
        const int stride = COPYB * 256;
        for (int i = bid * 256 + tid; i < N4; i += stride) {
            float4 a = __ldcs(mem0 + i);
            float4 c = __ldcs(mem1 + i);
            __stcs(dst + i,      a);
            __stcs(dst + N4 + i, c);
        }
    } else {
        // ---- gather CTA: one (b, split) per CTA ----
        const int id    = bid - COPYB;
        const int b     = id & (BB - 1);
        const int split = id >> 7;          // 0..SPLITS-1
        const int grp   = lane >> 3;        // quarter-warp: one k each
        const int gl    = lane & 7;
        const int j     = lane & 3;         // accumulator array for this lane

        // emb fragments as f32x2 pairs: lane owns float4 slots {gl,gl+8,gl+16,gl+24}
        const ulonglong2* e0p = reinterpret_cast<const ulonglong2*>(emb0) + b * 32;
        const ulonglong2* e1p = reinterpret_cast<const ulonglong2*>(emb1) + b * 32;
        ulonglong2 e0f[4], e1f[4];
#pragma unroll
        for (int i = 0; i < 4; i++) {
            e0f[i] = e0p[gl + 8*i];
            e1f[i] = e1p[gl + 8*i];
        }

        float accT = 0.f, acc1 = 0.f, accW = 0.f;

        for (int g = split * 8 + warp; g < NGRP; g += SPLITS * 8) {
            const int  k       = g * 4 + grp;
            const bool v_inter = (k < KTOT);
            int r = 0;
            if (v_inter) r = (k < 2) ? pos_idx[b*2 + k] : neg_idx[b*8192 + (k - 2)];
            const ulonglong2* M0 =
                reinterpret_cast<const ulonglong2*>(mem0 + (size_t)r * 32);
            const ulonglong2* M1 =
                reinterpret_cast<const ulonglong2*>(mem1 + (size_t)r * 32);

            unsigned long long s01 = 0ull, s10 = 0ull, si0 = 0ull, si1 = 0ull;
#pragma unroll
            for (int i = 0; i < 4; i++) {
                ulonglong2 m0 = M0[gl + 8*i];   // 8 lanes -> one 128B line
                ulonglong2 m1 = M1[gl + 8*i];
                ffma2(s01, m0.x, e1f[i].x);  ffma2(s01, m0.y, e1f[i].y);  // cij
                ffma2(si0, m0.x, e0f[i].x);  ffma2(si0, m0.y, e0f[i].y);  // intra0
                ffma2(s10, m1.x, e0f[i].x);  ffma2(s10, m1.y, e0f[i].y);  // cji
                ffma2(si1, m1.x, e1f[i].x);  ffma2(si1, m1.y, e1f[i].y);  // intra1
            }
            float f01 = hsum2(s01), f10 = hsum2(s10);
            float fi0 = hsum2(si0), fi1 = hsum2(si1);

            // reduce within the 8-lane quarter-warp
#pragma unroll
            for (int o = 4; o; o >>= 1) {
                f01 += __shfl_xor_sync(0xffffffffu, f01, o);
                f10 += __shfl_xor_sync(0xffffffffu, f10, o);
                fi0 += __shfl_xor_sync(0xffffffffu, fi0, o);
                fi1 += __shfl_xor_sync(0xffffffffu, fi1, o);
            }
            const float la  = f01 * TAU_INV;
            const float lc  = f10 * TAU_INV;
            const float lia = fi0 * TAU_INV;
            const float lib = fi1 * TAU_INV;

            if (g == 0) {                     // split 0, warp 0 only
                if (lane == 0) { g_spec[b][0] = la; g_spec[b][1] = lc; }   // k=0
                if (lane == 8) { g_spec[b][2] = la; g_spec[b][3] = lc;     // k=1
                                 g_spec[b][4] = lia; g_spec[b][5] = lib; }
            }

            // lane's (value, other) pair for its array j
            float v, o;
            if      (j == 0) { v = la;  o = lc;  }
            else if (j == 1) { v = lc;  o = la;  }
            else if (j == 2) { v = lia; o = lib; }
            else             { v = lib; o = lia; }
            const bool valid = (j < 2) ? v_inter : (v_inter && k >= 1);

            const float e3 = valid ? __expf(v * (1.0f/KDT_F)) : 0.f;  // exp(v/3)
            accT += e3;
            acc1 += e3 * e3 * e3;             // exp(v) = exp(v/3)^3
            accW += e3 * (v - o);
        }

        // xor4 folds the gl/gl+4 duplication (exact x2, halved below);
        // xor 8,16 fold the k-quarters.
#pragma unroll
        for (int o = 4; o <= 16; o <<= 1) {
            accT += __shfl_xor_sync(0xffffffffu, accT, o);
            acc1 += __shfl_xor_sync(0xffffffffu, acc1, o);
            accW += __shfl_xor_sync(0xffffffffu, accW, o);
        }

        __shared__ float sred[8][12];
        if (lane < 4) {
            sred[warp][lane*3 + 0] = accT * 0.5f;
            sred[warp][lane*3 + 1] = acc1 * 0.5f;
            sred[warp][lane*3 + 2] = accW * 0.5f;
        }
        __syncthreads();
        if (tid < 12) {
            float s = 0.f;
            for (int w = 0; w < 8; w++) s += sred[w][tid];   // fixed order
            g_part2[b][split][tid] = s;
        }
    }

    // ======================= fused finalize tail =======================
    __shared__ bool s_last;
    __syncthreads();
    if (tid == 0) {
        __threadfence();
        unsigned old = atomicAdd(&g_ctr, 1u);
        s_last = (old == TOTB - 1);
    }
    __syncthreads();
    if (!s_last) return;
    __threadfence();

    // ---- scalar reduce (threads 0..127) ----
    {
        float raw[4] = {0.f, 0.f, 0.f, 0.f};
        if (tid < BB) {
            float s2[12];
#pragma unroll
            for (int q = 0; q < 12; q++) {
                float a = 0.f;
                for (int sp = 0; sp < SPLITS; sp++) a += g_part2[tid][sp][q];
                s2[q] = a;
            }
            const float sAT = s2[0],  sA  = s2[1],  w1 = s2[2];
            const float sBT = s2[3],  sB  = s2[4],  w0 = s2[5];
            const float sIaT= s2[6],  sIa = s2[7],  w3 = s2[8];
            const float sIbT= s2[9],  sIb = s2[10], w2 = s2[11];
            const float LA  = logf(sA),  LB  = logf(sB);
            const float LIa = logf(sIa), LIb = logf(sIb);
            const float a0 = g_spec[tid][0], c0 = g_spec[tid][1];
            const float a1 = g_spec[tid][2], c1 = g_spec[tid][3];
            const float ia1 = g_spec[tid][4], ib1 = g_spec[tid][5];
            raw[0] = -(ia1 - LIa) - (ib1 - LIb);                     // vcl
            raw[1] = KDT_F * (w2 / sIbT + w3 / sIaT);                // soft_vcl
            raw[2] = -(0.5f*(a0+a1) - LA) - (0.5f*(c0+c1) - LB);     // icl
            raw[3] = KDT_F * (w0 / sBT + w1 / sAT);                  // soft_icl
        }
        __shared__ float scr[8][4];
#pragma unroll
        for (int q = 0; q < 4; q++) {
            float v = raw[q];
#pragma unroll
            for (int o = 16; o; o >>= 1) v += __shfl_xor_sync(0xffffffffu, v, o);
            if (lane == 0) scr[warp][q] = v;
        }
        __syncthreads();
        if (tid == 0) {
#pragma unroll
            for (int q = 0; q < 4; q++) {
                float v = 0.f;
                for (int w = 0; w < 8; w++) v += scr[w][q];
                out[q] = v / (float)BB;
            }
        }
    }

    // ---- momentum update: 256 warp-tasks (b, net), last-wins dedup ----
    for (int task = warp; task < 256; task += 8) {
        const int bb  = task & (BB - 1);
        const int net = task >> 7;
        const int r   = pos_idx[bb * 2];
        bool owner = true;
        for (int bp = bb + 1; bp < BB; bp++)
            if (pos_idx[bp * 2] == r) { owner = false; break; }
        if (!owner) continue;

        const float4* mem  = net ? mem1 : mem0;
        const float4* embp = reinterpret_cast<const float4*>(net ? emb1 : emb0);
        float4* dst = reinterpret_cast<float4*>(out + 4) + (size_t)net * N4;

        float4 m = mem[(size_t)r * 32 + lane];
        float4 e = embp[bb * 32 + lane];
        float4 u;
        u.x = 0.5f * (m.x + e.x);   // MOM = 0.5
        u.y = 0.5f * (m.y + e.y);
        u.z = 0.5f * (m.z + e.z);
        u.w = 0.5f * (m.w + e.w);
        float s2 = u.x*u.x + u.y*u.y + u.z*u.z + u.w*u.w;
#pragma unroll
        for (int o = 16; o; o >>= 1) s2 += __shfl_xor_sync(0xffffffffu, s2, o);
        const float inv = 1.0f / sqrtf(s2);
        u.x *= inv; u.y *= inv; u.z *= inv; u.w *= inv;
        dst[(size_t)r * 32 + lane] = u;
    }

    if (tid == 0) g_ctr = 0;   // reset for next graph replay
}

// ---------------------------------------------------------------------------
extern "C" void kernel_launch(void* const* d_in, const int* in_sizes, int n_in,
                              void* d_out, int out_size)
{
    const float* emb0    = (const float*)d_in[0];
    const float* emb1    = (const float*)d_in[1];
    const float* mem0    = (const float*)d_in[2];
    const float* mem1    = (const float*)d_in[3];
    const int*   pos_idx = (const int*)  d_in[4];
    const int*   neg_idx = (const int*)  d_in[5];
    float* out = (float*)d_out;

    // out layout: [vcl, soft_vcl, icl, soft_icl, new_mem0, new_mem1]
    big_kernel<<<TOTB, 256>>>(emb0, emb1,
                              (const float4*)mem0, (const float4*)mem1,
                              pos_idx, neg_idx, out);
}